// round 10
// baseline (speedup 1.0000x reference)
#include <cuda_runtime.h>
#include <cuda_bf16.h>
#include <math.h>

#define BATCH 8
#define NPTS  4096
#define KNN   20
#define FMAX  3.402823466e+38f

typedef unsigned long long u64t;

// packed f32x2 helpers (sm_100+): bit-exact fp32 FMA on both halves
__device__ __forceinline__ u64t pk2(float lo, float hi) {
    u64t r; asm("mov.b64 %0, {%1,%2};" : "=l"(r) : "f"(lo), "f"(hi)); return r;
}
__device__ __forceinline__ u64t fma2(u64t a, u64t b, u64t c) {
    u64t d; asm("fma.rn.f32x2 %0, %1, %2, %3;" : "=l"(d) : "l"(a), "l"(b), "l"(c)); return d;
}
__device__ __forceinline__ float2 up2(u64t v) {
    float2 f; asm("mov.b64 {%0,%1}, %2;" : "=f"(f.x), "=f"(f.y) : "l"(v)); return f;
}
union F4U { float4 f; u64t u[2]; };

__device__ __forceinline__ void cp_async16(void* dst_smem, const void* src_gmem) {
    unsigned sa = (unsigned)__cvta_generic_to_shared(dst_smem);
    asm volatile("cp.async.cg.shared.global [%0], [%1], 16;" :: "r"(sa), "l"(src_gmem));
}
__device__ __forceinline__ void cp_async_commit() {
    asm volatile("cp.async.commit_group;" ::: "memory");
}
__device__ __forceinline__ void cp_async_wait0() {
    asm volatile("cp.async.wait_group 0;" ::: "memory");
}
__device__ __forceinline__ void ldsm4(unsigned& r0, unsigned& r1, unsigned& r2, unsigned& r3,
                                      unsigned addr) {
    asm volatile("ldmatrix.sync.aligned.m8n8.x4.shared.b16 {%0,%1,%2,%3}, [%4];"
                 : "=r"(r0), "=r"(r1), "=r"(r2), "=r"(r3) : "r"(addr));
}
__device__ __forceinline__ void mma_bf16(float* c, unsigned a0, unsigned a1, unsigned a2,
                                         unsigned a3, unsigned b0, unsigned b1) {
    asm volatile(
        "mma.sync.aligned.m16n8k16.row.col.f32.bf16.bf16.f32 "
        "{%0,%1,%2,%3}, {%4,%5,%6,%7}, {%8,%9}, {%0,%1,%2,%3};"
        : "+f"(c[0]), "+f"(c[1]), "+f"(c[2]), "+f"(c[3])
        : "r"(a0), "r"(a1), "r"(a2), "r"(a3), "r"(b0), "r"(b1));
}
// split a pair of fp32 into packed bf16 hi + bf16 lo words
__device__ __forceinline__ void split2(float a, float b, unsigned& hi, unsigned& lo) {
    __nv_bfloat16 ha = __float2bfloat16(a), hb = __float2bfloat16(b);
    float ra = __bfloat162float(ha), rb = __bfloat162float(hb);
    __nv_bfloat16 la = __float2bfloat16(a - ra), lb = __float2bfloat16(b - rb);
    hi = (unsigned)__bfloat16_as_ushort(ha) | ((unsigned)__bfloat16_as_ushort(hb) << 16);
    lo = (unsigned)__bfloat16_as_ushort(la) | ((unsigned)__bfloat16_as_ushort(lb) << 16);
}

// ---------------- scratch (static device memory, no allocation) ----------------
__device__ float         g_x1[BATCH*NPTS*64];
__device__ float         g_d2[BATCH*NPTS];
__device__ int           g_idx1[BATCH*NPTS*KNN];
__device__ int           g_idx2[BATCH*NPTS*KNN];
__device__ float         g_A2[BATCH*NPTS*128];
__device__ float         g_C2[BATCH*NPTS*128];
__device__ float         g_x2[BATCH*NPTS*128];
__device__ float         g_pmax[BATCH*16*1024];
__device__ float         g_gmax[BATCH*1024];
__device__ float         g_hpart[BATCH*8*512];
__device__ __nv_bfloat16 g_xsplit[BATCH*NPTS*384];
__device__ __nv_bfloat16 g_wsplit[1024*384];
__device__ __align__(16) __nv_bfloat16 g_w2s[64*136];
__device__ __align__(16) __nv_bfloat16 g_w3s[64*136];

// Warp-parallel top-K insert. Entry n lives in lane n (n < KNN).
__device__ __forceinline__ void topk_insert(
    float cand, int cj, float& kdv, int& kiv, float& wv, int& wl, int lane)
{
    if (lane == wl) { kdv = cand; kiv = cj; }
    float md = (lane < KNN) ? kdv : -FMAX;
    int   mi = (lane < KNN) ? kiv : -1;
    int   ml = lane;
#pragma unroll
    for (int o = 16; o; o >>= 1) {
        float od = __shfl_xor_sync(0xffffffffu, md, o);
        int   oi = __shfl_xor_sync(0xffffffffu, mi, o);
        int   ol = __shfl_xor_sync(0xffffffffu, ml, o);
        bool t = (od > md) || (od == md && oi > mi);
        if (t) { md = od; mi = oi; ml = ol; }
    }
    wv = md; wl = ml;
}

// =================== kernel 1: kNN on raw 2-D points ===================
__global__ void __launch_bounds__(256) knn1_kernel(const float* __restrict__ data) {
    __shared__ float2 sp[NPTS];
    int b = blockIdx.y;
    const float2* dp = (const float2*)(data + (size_t)b * NPTS * 2);
    for (int t = threadIdx.x; t < NPTS; t += 256) sp[t] = dp[t];
    __syncthreads();

    int tid = threadIdx.x, lane = tid & 31, wid = tid >> 5;
    int row0 = blockIdx.x * 64 + wid * 8;

    float2 xi[8]; float d2i[8];
#pragma unroll
    for (int r = 0; r < 8; r++) {
        xi[r] = sp[row0 + r];
        d2i[r] = xi[r].x * xi[r].x + xi[r].y * xi[r].y;
    }
    float kd[8], wv[8]; int ki[8], wl[8];
#pragma unroll
    for (int r = 0; r < 8; r++) { kd[r] = FMAX; ki[r] = 0x7fffffff; wv[r] = FMAX; wl[r] = 0; }

    for (int jc = 0; jc < NPTS / 32; jc++) {
        int jb = jc * 32;
        float2 xj = sp[jb + lane];
        float d2j = xj.x * xj.x + xj.y * xj.y;
#pragma unroll
        for (int r = 0; r < 8; r++) {
            float d = d2i[r] + d2j - 2.0f * (xi[r].x * xj.x + xi[r].y * xj.y);
            unsigned m = __ballot_sync(0xffffffffu, d < wv[r]);
            while (m) {
                int s = __ffs(m) - 1;
                float cand = __shfl_sync(0xffffffffu, d, s);
                topk_insert(cand, jb + s, kd[r], ki[r], wv[r], wl[r], lane);
                m &= ~(1u << s);
                m &= __ballot_sync(0xffffffffu, d < wv[r]);
            }
        }
    }
#pragma unroll
    for (int r = 0; r < 8; r++)
        if (lane < KNN)
            g_idx1[((size_t)b * NPTS + row0 + r) * KNN + lane] = ki[r];
}

// =================== kernel 2a: split+transpose W2/W3 to bf16 hi/lo ===================
__global__ void __launch_bounds__(256) splitw23_kernel(
    const float* __restrict__ c1w2, const float* __restrict__ c1w3)
{
    int idx = blockIdx.x * 256 + threadIdx.x;      // 8192
    int mat = idx >> 12, e = idx & 4095;
    int k = e >> 6, n = e & 63;
    const float* src = mat ? c1w3 : c1w2;
    float v = src[k * 64 + n];
    __nv_bfloat16 h = __float2bfloat16(v);
    __nv_bfloat16 l = __float2bfloat16(v - __bfloat162float(h));
    __nv_bfloat16* dst = mat ? g_w3s : g_w2s;
    dst[n * 136 + k] = h;
    dst[n * 136 + 64 + k] = l;
}

// =================== kernel 2b: EdgeConv1 via split-bf16 mma.sync ===================
#define E1_SW1 0
#define E1_SB1 256
#define E1_SB2 320
#define E1_SB3 384
#define E1_SPC 448
#define E1_SXJ 960
#define E1B_W2 5120
#define E1B_W3 22528
#define E1B_H  39936
#define E1_BYTES (E1B_H + 160*272)

__global__ void __launch_bounds__(256) edge1_kernel(
    const float* __restrict__ data,
    const float* __restrict__ c1w1, const float* __restrict__ c1b1,
    const float* __restrict__ c1b2, const float* __restrict__ c1b3)
{
    extern __shared__ float sm[];
    char* smc = (char*)sm;
    unsigned sbase = (unsigned)__cvta_generic_to_shared(smc);
    int tid = threadIdx.x, lane = tid & 31, wid = tid >> 5;
    int wn = wid & 3, wm = wid >> 2;
    int base = blockIdx.x * 8;
    int b = base >> 12;

    if (tid < 256) sm[E1_SW1 + tid] = c1w1[tid];
    if (tid < 64) {
        sm[E1_SB1 + tid] = c1b1[tid];
        sm[E1_SB2 + tid] = c1b2[tid];
        sm[E1_SB3 + tid] = c1b3[tid];
    }
    for (int q = tid; q < 1088; q += 256)
        ((uint4*)(smc + E1B_W2))[q] = ((const uint4*)g_w2s)[q];
    for (int q = tid; q < 1088; q += 256)
        ((uint4*)(smc + E1B_W3))[q] = ((const uint4*)g_w3s)[q];
    __syncthreads();

    for (int idx = tid; idx < 512; idx += 256) {
        int p = idx >> 6, c = idx & 63;
        float xi0 = data[(size_t)(base + p) * 2 + 0];
        float xi1 = data[(size_t)(base + p) * 2 + 1];
        float wa = sm[E1_SW1 + c] - sm[E1_SW1 + 128 + c];
        float wb = sm[E1_SW1 + 64 + c] - sm[E1_SW1 + 192 + c];
        sm[E1_SPC + p * 64 + c] = fmaf(xi0, wa, fmaf(xi1, wb, sm[E1_SB1 + c]));
    }
    if (tid < 160) {
        int p = tid / 20, e = tid % 20;
        int j = g_idx1[(size_t)(base + p) * KNN + e];
        int gj = (b << 12) + j;
        sm[E1_SXJ + 2 * tid + 0] = data[(size_t)gj * 2 + 0];
        sm[E1_SXJ + 2 * tid + 1] = data[(size_t)gj * 2 + 1];
    }
    __syncthreads();

    for (int idx = tid; idx < 160 * 32; idx += 256) {
        int row = idx >> 5, cq = idx & 31;
        int p = row / 20, c0 = 2 * cq;
        float xj0 = sm[E1_SXJ + 2 * row], xj1 = sm[E1_SXJ + 2 * row + 1];
        float h0 = fmaxf(fmaf(xj0, sm[E1_SW1 + 128 + c0],
                     fmaf(xj1, sm[E1_SW1 + 192 + c0], sm[E1_SPC + p * 64 + c0])), 0.0f);
        float h1 = fmaxf(fmaf(xj0, sm[E1_SW1 + 128 + c0 + 1],
                     fmaf(xj1, sm[E1_SW1 + 192 + c0 + 1], sm[E1_SPC + p * 64 + c0 + 1])), 0.0f);
        unsigned hi, lo; split2(h0, h1, hi, lo);
        *(unsigned*)(smc + E1B_H + row * 272 + c0 * 2) = hi;
        *(unsigned*)(smc + E1B_H + row * 272 + 128 + c0 * 2) = lo;
    }
    __syncthreads();

    int arow = (lane & 7) + ((lane >> 3) & 1) * 8;
    int akb  = ((lane >> 4) & 1) * 16;
    int brow = (lane & 7) + ((lane >> 4) & 1) * 8;
    int bkb  = ((lane >> 3) & 1) * 16;
    unsigned aBase  = sbase + E1B_H  + (unsigned)(wm * 80 + arow) * 272 + akb;
    unsigned b2Base = sbase + E1B_W2 + (unsigned)(wn * 16 + brow) * 272 + bkb;
    unsigned b3Base = sbase + E1B_W3 + (unsigned)(wn * 16 + brow) * 272 + bkb;

    float bias2[2][2], bias3[2][2];
#pragma unroll
    for (int nf = 0; nf < 2; nf++) {
        int c = wn * 16 + nf * 8 + 2 * (lane & 3);
        bias2[nf][0] = sm[E1_SB2 + c]; bias2[nf][1] = sm[E1_SB2 + c + 1];
        bias3[nf][0] = sm[E1_SB3 + c]; bias3[nf][1] = sm[E1_SB3 + c + 1];
    }

    // ---- GEMM 1: H2 = relu(H1 @ W2 + b2) ----
    {
        float acc[5][2][4];
#pragma unroll
        for (int m = 0; m < 5; m++)
#pragma unroll
            for (int nf = 0; nf < 2; nf++)
#pragma unroll
                for (int e = 0; e < 4; e++) acc[m][nf][e] = 0.0f;
#pragma unroll
        for (int t = 0; t < 12; t++) {
            int ts = (t < 4) ? t : (t < 8 ? t - 4 : t - 8);
            int aoff = ((t >= 4 && t < 8) ? 128 : 0) + ts * 32;
            int boff = ((t >= 8) ? 128 : 0) + ts * 32;
            unsigned B0[4];
            ldsm4(B0[0], B0[1], B0[2], B0[3], b2Base + boff);
#pragma unroll
            for (int m = 0; m < 5; m++) {
                unsigned A0[4];
                ldsm4(A0[0], A0[1], A0[2], A0[3], aBase + m * (16 * 272) + aoff);
                mma_bf16(acc[m][0], A0[0], A0[1], A0[2], A0[3], B0[0], B0[1]);
                mma_bf16(acc[m][1], A0[0], A0[1], A0[2], A0[3], B0[2], B0[3]);
            }
        }
        __syncthreads();
#pragma unroll
        for (int m = 0; m < 5; m++) {
            int r0 = wm * 80 + m * 16 + (lane >> 2);
#pragma unroll
            for (int nf = 0; nf < 2; nf++) {
                int c0 = wn * 16 + nf * 8 + 2 * (lane & 3);
                float v0 = fmaxf(acc[m][nf][0] + bias2[nf][0], 0.0f);
                float v1 = fmaxf(acc[m][nf][1] + bias2[nf][1], 0.0f);
                float v2 = fmaxf(acc[m][nf][2] + bias2[nf][0], 0.0f);
                float v3 = fmaxf(acc[m][nf][3] + bias2[nf][1], 0.0f);
                unsigned hi, lo;
                split2(v0, v1, hi, lo);
                *(unsigned*)(smc + E1B_H + r0 * 272 + c0 * 2) = hi;
                *(unsigned*)(smc + E1B_H + r0 * 272 + 128 + c0 * 2) = lo;
                split2(v2, v3, hi, lo);
                *(unsigned*)(smc + E1B_H + (r0 + 8) * 272 + c0 * 2) = hi;
                *(unsigned*)(smc + E1B_H + (r0 + 8) * 272 + 128 + c0 * 2) = lo;
            }
        }
    }
    __syncthreads();

    // ---- GEMM 2: H3 = H2 @ W3 + b3 ----
    {
        float acc[5][2][4];
#pragma unroll
        for (int m = 0; m < 5; m++)
#pragma unroll
            for (int nf = 0; nf < 2; nf++)
#pragma unroll
                for (int e = 0; e < 4; e++) acc[m][nf][e] = 0.0f;
#pragma unroll
        for (int t = 0; t < 12; t++) {
            int ts = (t < 4) ? t : (t < 8 ? t - 4 : t - 8);
            int aoff = ((t >= 4 && t < 8) ? 128 : 0) + ts * 32;
            int boff = ((t >= 8) ? 128 : 0) + ts * 32;
            unsigned B0[4];
            ldsm4(B0[0], B0[1], B0[2], B0[3], b3Base + boff);
#pragma unroll
            for (int m = 0; m < 5; m++) {
                unsigned A0[4];
                ldsm4(A0[0], A0[1], A0[2], A0[3], aBase + m * (16 * 272) + aoff);
                mma_bf16(acc[m][0], A0[0], A0[1], A0[2], A0[3], B0[0], B0[1]);
                mma_bf16(acc[m][1], A0[0], A0[1], A0[2], A0[3], B0[2], B0[3]);
            }
        }
        __syncthreads();
        float* H3f = (float*)(smc + E1B_H);
#pragma unroll
        for (int m = 0; m < 5; m++) {
            int r0 = wm * 80 + m * 16 + (lane >> 2);
#pragma unroll
            for (int nf = 0; nf < 2; nf++) {
                int c0 = wn * 16 + nf * 8 + 2 * (lane & 3);
                *(float2*)&H3f[r0 * 68 + c0] =
                    make_float2(acc[m][nf][0] + bias3[nf][0], acc[m][nf][1] + bias3[nf][1]);
                *(float2*)&H3f[(r0 + 8) * 68 + c0] =
                    make_float2(acc[m][nf][2] + bias3[nf][0], acc[m][nf][3] + bias3[nf][1]);
            }
        }
    }
    __syncthreads();

    {
        const float* H3f = (const float*)(smc + E1B_H);
        for (int idx = tid; idx < 512; idx += 256) {
            int p = idx >> 6, c = idx & 63;
            float mx = H3f[(p * 20) * 68 + c];
#pragma unroll
            for (int e = 1; e < 20; e++) mx = fmaxf(mx, H3f[(p * 20 + e) * 68 + c]);
            g_x1[(size_t)(base + p) * 64 + c] = mx;
            sm[E1_SPC + idx] = mx;
        }
    }
    __syncthreads();
    {
        int w = tid >> 5;
        float v0 = sm[E1_SPC + w * 64 + lane];
        float v1 = sm[E1_SPC + w * 64 + 32 + lane];
        float s = v0 * v0 + v1 * v1;
#pragma unroll
        for (int o = 16; o; o >>= 1) s += __shfl_xor_sync(0xffffffffu, s, o);
        if (lane == 0) g_d2[base + w] = s;
    }
}

// =================== kernel 3: EdgeConv2 per-point linear parts ===================
__global__ void __launch_bounds__(128) prep2_kernel(
    const float* __restrict__ c2w1, const float* __restrict__ c2b1)
{
    __shared__ float sx[8][64];
    int c = threadIdx.x;
    int base = blockIdx.x * 8;
    for (int idx = c; idx < 512; idx += 128) {
        int p = idx >> 6, d = idx & 63;
        sx[p][d] = g_x1[(size_t)(base + p) * 64 + d];
    }
    __syncthreads();
    float accA[8], accC[8];
    float bc = c2b1[c];
#pragma unroll
    for (int p = 0; p < 8; p++) { accA[p] = bc; accC[p] = 0.0f; }
    for (int d = 0; d < 64; d++) {
        float wt = c2w1[d * 128 + c];
        float wbv = c2w1[(d + 64) * 128 + c];
        float wd = wt - wbv;
#pragma unroll
        for (int p = 0; p < 8; p++) {
            float xv = sx[p][d];
            accA[p] = fmaf(xv, wd, accA[p]);
            accC[p] = fmaf(xv, wbv, accC[p]);
        }
    }
#pragma unroll
    for (int p = 0; p < 8; p++) {
        g_A2[(size_t)(base + p) * 128 + c] = accA[p];
        g_C2[(size_t)(base + p) * 128 + c] = accC[p];
    }
}

// =================== kernel 4: knn2 — 8 i-rows/warp, 64 rows/block (crossbar halved) ===================
#define KP 68
#define KN2_AS   (64 * KP)
#define KN2_BS   (128 * KP)
#define KN2_SMEM_FLOATS (KN2_AS + 2 * KN2_BS + 2 * 128)
#define KN2_SMEM_BYTES  (KN2_SMEM_FLOATS * 4)

__global__ void __launch_bounds__(256, 1) knn2_kernel() {
    extern __shared__ float sm[];
    float* As   = sm;
    float* Bs0  = sm + KN2_AS;
    float* d2s0 = sm + KN2_AS + 2 * KN2_BS;

    int b = blockIdx.y;
    int it0 = blockIdx.x * 64;
    int tid = threadIdx.x, lane = tid & 31, wid = tid >> 5;
    const float* xb = g_x1 + (size_t)b * NPTS * 64;

#pragma unroll
    for (int t = 0; t < 4; t++) {
        int idx = tid + t * 256;
        int i = idx >> 4, kq = idx & 15;
        *(float4*)(As + i * KP + kq * 4) =
            *(const float4*)(xb + (size_t)(it0 + i) * 64 + kq * 4);
    }
    float d2i[8];
#pragma unroll
    for (int r = 0; r < 8; r++) d2i[r] = g_d2[b * NPTS + it0 + wid * 8 + r];

    float kd[8], wv[8]; int ki[8], wl[8];
#pragma unroll
    for (int r = 0; r < 8; r++) { kd[r] = FMAX; ki[r] = 0x7fffffff; wv[r] = FMAX; wl[r] = 0; }

    {
        float* B = Bs0;
#pragma unroll
        for (int t = 0; t < 8; t++) {
            int idx = tid + t * 256;
            int j = idx >> 4, kq = idx & 15;
            cp_async16(B + j * KP + kq * 4, xb + (size_t)j * 64 + kq * 4);
        }
        if (tid < 32) cp_async16(d2s0 + tid * 4, g_d2 + b * NPTS + tid * 4);
        cp_async_commit();
    }

    for (int jt = 0; jt < 32; jt++) {
        int buf = jt & 1;
        cp_async_wait0();
        __syncthreads();

        if (jt + 1 < 32) {
            int jb1 = (jt + 1) * 128;
            float* B = Bs0 + (buf ^ 1) * KN2_BS;
#pragma unroll
            for (int t = 0; t < 8; t++) {
                int idx = tid + t * 256;
                int j = idx >> 4, kq = idx & 15;
                cp_async16(B + j * KP + kq * 4, xb + (size_t)(jb1 + j) * 64 + kq * 4);
            }
            if (tid < 32) cp_async16(d2s0 + (buf ^ 1) * 128 + tid * 4,
                                     g_d2 + b * NPTS + jb1 + tid * 4);
            cp_async_commit();
        }

        const float* B = Bs0 + buf * KN2_BS;
        const float* d2s = d2s0 + buf * 128;
        int jb = jt * 128;

        u64t acc2[8][4];
#pragma unroll
        for (int r = 0; r < 8; r++)
#pragma unroll
            for (int jj = 0; jj < 4; jj++) acc2[r][jj] = 0ull;

#pragma unroll 4
        for (int kq = 0; kq < 16; kq++) {
            F4U bb[4];
#pragma unroll
            for (int jj = 0; jj < 4; jj++)
                bb[jj].f = *(const float4*)(B + (jj * 32 + lane) * KP + kq * 4);
#pragma unroll
            for (int r = 0; r < 8; r++) {
                F4U a;
                a.f = *(const float4*)(As + (wid * 8 + r) * KP + kq * 4);
#pragma unroll
                for (int jj = 0; jj < 4; jj++) {
                    acc2[r][jj] = fma2(a.u[0], bb[jj].u[0], acc2[r][jj]);
                    acc2[r][jj] = fma2(a.u[1], bb[jj].u[1], acc2[r][jj]);
                }
            }
        }

        float d2jv[4];
#pragma unroll
        for (int jj = 0; jj < 4; jj++) d2jv[jj] = d2s[jj * 32 + lane];

#pragma unroll
        for (int r = 0; r < 8; r++) {
#pragma unroll
            for (int jj = 0; jj < 4; jj++) {
                float2 v = up2(acc2[r][jj]);
                float dv = d2i[r] + d2jv[jj] - 2.0f * (v.x + v.y);
                unsigned m = __ballot_sync(0xffffffffu, dv < wv[r]);
                while (m) {
                    int s = __ffs(m) - 1;
                    float cand = __shfl_sync(0xffffffffu, dv, s);
                    topk_insert(cand, jb + jj * 32 + s, kd[r], ki[r], wv[r], wl[r], lane);
                    m &= ~(1u << s);
                    m &= __ballot_sync(0xffffffffu, dv < wv[r]);
                }
            }
        }
    }
#pragma unroll
    for (int r = 0; r < 8; r++)
        if (lane < KNN)
            g_idx2[((size_t)b * NPTS + it0 + wid * 8 + r) * KNN + lane] = ki[r];
}

// =================== kernel 5: EdgeConv2 gather-max (4 points/block) ===================
__global__ void __launch_bounds__(128) edge2max_kernel() {
    __shared__ int sj[4][KNN];
    int p0 = blockIdx.x * 4;
    int c = threadIdx.x;
    if (c < 4 * KNN) sj[c / KNN][c % KNN] = g_idx2[(size_t)(p0 + c / KNN) * KNN + c % KNN];
    __syncthreads();
#pragma unroll
    for (int q = 0; q < 4; q++) {
        int gp = p0 + q;
        int b = gp >> 12;
        float m = -FMAX;
#pragma unroll
        for (int e = 0; e < KNN; e++)
            m = fmaxf(m, g_C2[((size_t)b * NPTS + sj[q][e]) * 128 + c]);
        g_x2[(size_t)gp * 128 + c] = g_A2[(size_t)gp * 128 + c] + m;
    }
}

// =================== kernel 6a: split [x1|x2] rows into hi/lo bf16 ===================
__global__ void __launch_bounds__(256) splitx_kernel() {
    int idx = blockIdx.x * 256 + threadIdx.x;
    int row = idx / 192, k = idx - row * 192;
    float v = (k < 64) ? g_x1[(size_t)row * 64 + k]
                       : g_x2[(size_t)row * 128 + (k - 64)];
    __nv_bfloat16 h = __float2bfloat16(v);
    __nv_bfloat16 l = __float2bfloat16(v - __bfloat162float(h));
    g_xsplit[(size_t)row * 384 + k] = h;
    g_xsplit[(size_t)row * 384 + 192 + k] = l;
}

// =================== kernel 6b: split + transpose lin1_w ===================
__global__ void __launch_bounds__(256) splitw_kernel(const float* __restrict__ lin1_w) {
    int idx = blockIdx.x * 256 + threadIdx.x;
    int n = idx / 192, k = idx - n * 192;
    float v = lin1_w[(size_t)k * 1024 + n];
    __nv_bfloat16 h = __float2bfloat16(v);
    __nv_bfloat16 l = __float2bfloat16(v - __bfloat162float(h));
    g_wsplit[(size_t)n * 384 + k] = h;
    g_wsplit[(size_t)n * 384 + 192 + k] = l;
}

// =================== kernel 6c: lin1 via split-bf16 mma.sync + fused row-max ===================
#define LM_STR  784
#define LM_WS   0
#define LM_XS   (128 * LM_STR)
#define LM_XSZ  (32 * LM_STR)
#define LM_SMEM (LM_XS + 2 * LM_XSZ)

__global__ void __launch_bounds__(256, 1) lin1mma_kernel() {
    extern __shared__ char smc[];
    unsigned sbase = (unsigned)__cvta_generic_to_shared(smc);
    int tid = threadIdx.x, lane = tid & 31, w = tid >> 5;
    int cc = blockIdx.x, rc = blockIdx.y, b = blockIdx.z;
    const __nv_bfloat16* xs = g_xsplit + (size_t)(b * NPTS + rc * 1024) * 384;
    const __nv_bfloat16* ws = g_wsplit + (size_t)cc * 128 * 384;

    for (int q = tid; q < 128 * 48; q += 256) {
        int n = q / 48, u = q - n * 48;
        cp_async16(smc + LM_WS + n * LM_STR + u * 16, (const char*)(ws + (size_t)n * 384) + u * 16);
    }
    for (int q = tid; q < 32 * 48; q += 256) {
        int r = q / 48, u = q - r * 48;
        cp_async16(smc + LM_XS + r * LM_STR + u * 16, (const char*)(xs + (size_t)r * 384) + u * 16);
    }
    cp_async_commit();

    int arow = (lane & 7) + ((lane >> 3) & 1) * 8;
    int akb  = ((lane >> 4) & 1) * 16;
    int brow = (lane & 7) + ((lane >> 4) & 1) * 8;
    int bkb  = ((lane >> 3) & 1) * 16;
    unsigned bAddr0 = sbase + LM_WS + (unsigned)(w * 16 + brow) * LM_STR + bkb;

    float rm[2][2];
#pragma unroll
    for (int nf = 0; nf < 2; nf++) { rm[nf][0] = -FMAX; rm[nf][1] = -FMAX; }

    for (int ch = 0; ch < 32; ch++) {
        int buf = ch & 1;
        cp_async_wait0();
        __syncthreads();

        if (ch + 1 < 32) {
            char* Xd = smc + LM_XS + (buf ^ 1) * LM_XSZ;
            const __nv_bfloat16* src = xs + (size_t)(ch + 1) * 32 * 384;
            for (int q = tid; q < 32 * 48; q += 256) {
                int r = q / 48, u = q - r * 48;
                cp_async16(Xd + r * LM_STR + u * 16, (const char*)(src + (size_t)r * 384) + u * 16);
            }
            cp_async_commit();
        }

        unsigned aAddr0 = sbase + LM_XS + buf * LM_XSZ + (unsigned)arow * LM_STR + akb;
        float acc[2][2][4];
#pragma unroll
        for (int m = 0; m < 2; m++)
#pragma unroll
            for (int nf = 0; nf < 2; nf++)
#pragma unroll
                for (int e = 0; e < 4; e++) acc[m][nf][e] = 0.0f;

#pragma unroll
        for (int t = 0; t < 36; t++) {
            int aoff = ((t < 12) ? t : t - 12) * 32;
            int boff = ((t < 24) ? t : t - 24) * 32;
            unsigned A0[4], A1[4], B0[4];
            ldsm4(A0[0], A0[1], A0[2], A0[3], aAddr0 + aoff);
            ldsm4(A1[0], A1[1], A1[2], A1[3], aAddr0 + 16 * LM_STR + aoff);
            ldsm4(B0[0], B0[1], B0[2], B0[3], bAddr0 + boff);
            mma_bf16(acc[0][0], A0[0], A0[1], A0[2], A0[3], B0[0], B0[1]);
            mma_bf16(acc[0][1], A0[0], A0[1], A0[2], A0[3], B0[2], B0[3]);
            mma_bf16(acc[1][0], A1[0], A1[1], A1[2], A1[3], B0[0], B0[1]);
            mma_bf16(acc[1][1], A1[0], A1[1], A1[2], A1[3], B0[2], B0[3]);
        }
#pragma unroll
        for (int nf = 0; nf < 2; nf++) {
            rm[nf][0] = fmaxf(rm[nf][0], fmaxf(fmaxf(acc[0][nf][0], acc[0][nf][2]),
                                               fmaxf(acc[1][nf][0], acc[1][nf][2])));
            rm[nf][1] = fmaxf(rm[nf][1], fmaxf(fmaxf(acc[0][nf][1], acc[0][nf][3]),
                                               fmaxf(acc[1][nf][1], acc[1][nf][3])));
        }
    }
#pragma unroll
    for (int o = 4; o <= 16; o <<= 1)
#pragma unroll
        for (int nf = 0; nf < 2; nf++) {
            rm[nf][0] = fmaxf(rm[nf][0], __shfl_xor_sync(0xffffffffu, rm[nf][0], o));
            rm[nf][1] = fmaxf(rm[nf][1], __shfl_xor_sync(0xffffffffu, rm[nf][1], o));
        }
    if (lane < 4) {
#pragma unroll
        for (int nf = 0; nf < 2; nf++) {
            int col = cc * 128 + w * 16 + nf * 8 + 2 * lane;
            g_pmax[((size_t)b * 16 + rc) * 1024 + col]     = rm[nf][0];
            g_pmax[((size_t)b * 16 + rc) * 1024 + col + 1] = rm[nf][1];
        }
    }
}

// =================== kernel 7: reduce partial maxes + bias ===================
__global__ void __launch_bounds__(1024) redmax_kernel(const float* __restrict__ lin1_b) {
    int b = blockIdx.x, c = threadIdx.x;
    float m = -FMAX;
#pragma unroll
    for (int t = 0; t < 4; t++) m = fmaxf(m, g_pmax[((size_t)b * 16 + t) * 1024 + c]);
    g_gmax[b * 1024 + c] = m + lin1_b[c];
}

// =================== kernel 8a: head GEMV1 split over k-chunks ===================
__global__ void __launch_bounds__(512) head1_kernel(const float* __restrict__ mw1) {
    __shared__ float sg[128];
    int kc = blockIdx.x, b = blockIdx.y, t = threadIdx.x;
    if (t < 128) sg[t] = g_gmax[b * 1024 + kc * 128 + t];
    __syncthreads();
    float acc = 0.0f;
#pragma unroll 4
    for (int d = 0; d < 128; d++)
        acc = fmaf(sg[d], mw1[(size_t)(kc * 128 + d) * 512 + t], acc);
    g_hpart[(size_t)(b * 8 + kc) * 512 + t] = acc;
}

// =================== kernel 8b: head rest + log_softmax ===================
__global__ void __launch_bounds__(512) head2_kernel(
    const float* __restrict__ mb1,
    const float* __restrict__ mw2, const float* __restrict__ mb2,
    const float* __restrict__ mw3, const float* __restrict__ mb3,
    float* __restrict__ out)
{
    __shared__ float s1[512];
    __shared__ float s2[256];
    __shared__ float s3[10];
    int b = blockIdx.x, t = threadIdx.x;

    float a = mb1[t];
#pragma unroll
    for (int kc = 0; kc < 8; kc++) a += g_hpart[(size_t)(b * 8 + kc) * 512 + t];
    s1[t] = fmaxf(a, 0.0f);
    __syncthreads();

    if (t < 256) {
        float acc = mb2[t];
#pragma unroll 4
        for (int d = 0; d < 512; d++) acc = fmaf(s1[d], mw2[d * 256 + t], acc);
        s2[t] = fmaxf(acc, 0.0f);
    }
    __syncthreads();

    if (t < 10) {
        float acc = mb3[t];
        for (int d = 0; d < 256; d++) acc = fmaf(s2[d], mw3[d * 10 + t], acc);
        s3[t] = acc;
    }
    __syncthreads();

    if (t == 0) {
        float mx = s3[0];
        for (int j = 1; j < 10; j++) mx = fmaxf(mx, s3[j]);
        float s = 0.0f;
        for (int j = 0; j < 10; j++) s += expf(s3[j] - mx);
        float l = logf(s) + mx;
        for (int j = 0; j < 10; j++) out[b * 10 + j] = s3[j] - l;
    }
}

// =================== launch ===================
extern "C" void kernel_launch(void* const* d_in, const int* in_sizes, int n_in,
                              void* d_out, int out_size) {
    const float* data   = (const float*)d_in[0];
    const float* c1w1   = (const float*)d_in[1];
    const float* c1b1   = (const float*)d_in[2];
    const float* c1w2   = (const float*)d_in[3];
    const float* c1b2   = (const float*)d_in[4];
    const float* c1w3   = (const float*)d_in[5];
    const float* c1b3   = (const float*)d_in[6];
    const float* c2w1   = (const float*)d_in[7];
    const float* c2b1   = (const float*)d_in[8];
    const float* lin1_w = (const float*)d_in[9];
    const float* lin1_b = (const float*)d_in[10];
    const float* mw1    = (const float*)d_in[11];
    const float* mb1    = (const float*)d_in[12];
    const float* mw2    = (const float*)d_in[13];
    const float* mb2    = (const float*)d_in[14];
    const float* mw3    = (const float*)d_in[15];
    const float* mb3    = (const float*)d_in[16];
    float* out = (float*)d_out;

    cudaFuncSetAttribute(edge1_kernel, cudaFuncAttributeMaxDynamicSharedMemorySize, E1_BYTES);
    cudaFuncSetAttribute(knn2_kernel, cudaFuncAttributeMaxDynamicSharedMemorySize, KN2_SMEM_BYTES);
    cudaFuncSetAttribute(lin1mma_kernel, cudaFuncAttributeMaxDynamicSharedMemorySize, LM_SMEM);

    knn1_kernel<<<dim3(64, 8), 256>>>(data);
    splitw23_kernel<<<32, 256>>>(c1w2, c1w3);
    edge1_kernel<<<BATCH * NPTS / 8, 256, E1_BYTES>>>(data, c1w1, c1b1, c1b2, c1b3);
    prep2_kernel<<<BATCH * NPTS / 8, 128>>>(c2w1, c2b1);
    knn2_kernel<<<dim3(64, 8), 256, KN2_SMEM_BYTES>>>();
    edge2max_kernel<<<BATCH * NPTS / 4, 128>>>();
    splitx_kernel<<<BATCH * NPTS * 192 / 256, 256>>>();
    splitw_kernel<<<1024 * 192 / 256, 256>>>(lin1_w);
    lin1mma_kernel<<<dim3(8, 4, 8), 256, LM_SMEM>>>();
    redmax_kernel<<<8, 1024>>>(lin1_b);
    head1_kernel<<<dim3(8, 8), 512>>>(mw1);
    head2_kernel<<<8, 512>>>(mb1, mw2, mb2, mw3, mb3, out);
}

// round 11
// speedup vs baseline: 1.1939x; 1.1939x over previous
#include <cuda_runtime.h>
#include <cuda_bf16.h>
#include <math.h>

#define BATCH 8
#define NPTS  4096
#define KNN   20
#define FMAX  3.402823466e+38f

typedef unsigned long long u64t;

// packed f32x2 helpers (sm_100+): bit-exact fp32 FMA on both halves
__device__ __forceinline__ u64t pk2(float lo, float hi) {
    u64t r; asm("mov.b64 %0, {%1,%2};" : "=l"(r) : "f"(lo), "f"(hi)); return r;
}
__device__ __forceinline__ u64t fma2(u64t a, u64t b, u64t c) {
    u64t d; asm("fma.rn.f32x2 %0, %1, %2, %3;" : "=l"(d) : "l"(a), "l"(b), "l"(c)); return d;
}
__device__ __forceinline__ float2 up2(u64t v) {
    float2 f; asm("mov.b64 {%0,%1}, %2;" : "=f"(f.x), "=f"(f.y) : "l"(v)); return f;
}
union F4U { float4 f; u64t u[2]; };

__device__ __forceinline__ void cp_async16(void* dst_smem, const void* src_gmem) {
    unsigned sa = (unsigned)__cvta_generic_to_shared(dst_smem);
    asm volatile("cp.async.cg.shared.global [%0], [%1], 16;" :: "r"(sa), "l"(src_gmem));
}
__device__ __forceinline__ void cp_async_commit() {
    asm volatile("cp.async.commit_group;" ::: "memory");
}
__device__ __forceinline__ void cp_async_wait0() {
    asm volatile("cp.async.wait_group 0;" ::: "memory");
}
__device__ __forceinline__ void ldsm4(unsigned& r0, unsigned& r1, unsigned& r2, unsigned& r3,
                                      unsigned addr) {
    asm volatile("ldmatrix.sync.aligned.m8n8.x4.shared.b16 {%0,%1,%2,%3}, [%4];"
                 : "=r"(r0), "=r"(r1), "=r"(r2), "=r"(r3) : "r"(addr));
}
__device__ __forceinline__ void mma_bf16(float* c, unsigned a0, unsigned a1, unsigned a2,
                                         unsigned a3, unsigned b0, unsigned b1) {
    asm volatile(
        "mma.sync.aligned.m16n8k16.row.col.f32.bf16.bf16.f32 "
        "{%0,%1,%2,%3}, {%4,%5,%6,%7}, {%8,%9}, {%0,%1,%2,%3};"
        : "+f"(c[0]), "+f"(c[1]), "+f"(c[2]), "+f"(c[3])
        : "r"(a0), "r"(a1), "r"(a2), "r"(a3), "r"(b0), "r"(b1));
}
// split a pair of fp32 into packed bf16 hi + bf16 lo words
__device__ __forceinline__ void split2(float a, float b, unsigned& hi, unsigned& lo) {
    __nv_bfloat16 ha = __float2bfloat16(a), hb = __float2bfloat16(b);
    float ra = __bfloat162float(ha), rb = __bfloat162float(hb);
    __nv_bfloat16 la = __float2bfloat16(a - ra), lb = __float2bfloat16(b - rb);
    hi = (unsigned)__bfloat16_as_ushort(ha) | ((unsigned)__bfloat16_as_ushort(hb) << 16);
    lo = (unsigned)__bfloat16_as_ushort(la) | ((unsigned)__bfloat16_as_ushort(lb) << 16);
}

// ---------------- scratch (static device memory, no allocation) ----------------
__device__ float         g_x1[BATCH*NPTS*64];
__device__ float         g_d2[BATCH*NPTS];
__device__ int           g_idx1[BATCH*NPTS*KNN];
__device__ int           g_idx2[BATCH*NPTS*KNN];
__device__ float         g_A2[BATCH*NPTS*128];
__device__ float         g_C2[BATCH*NPTS*128];
__device__ float         g_x2[BATCH*NPTS*128];
__device__ float         g_pmax[BATCH*16*1024];
__device__ float         g_gmax[BATCH*1024];
__device__ float         g_hpart[BATCH*8*512];
__device__ __nv_bfloat16 g_xsplit[BATCH*NPTS*384];
__device__ __nv_bfloat16 g_wsplit[1024*384];
__device__ __align__(16) __nv_bfloat16 g_w2s[64*136];
__device__ __align__(16) __nv_bfloat16 g_w3s[64*136];

// Warp-parallel top-K insert. Entry n lives in lane n (n < KNN).
__device__ __forceinline__ void topk_insert(
    float cand, int cj, float& kdv, int& kiv, float& wv, int& wl, int lane)
{
    if (lane == wl) { kdv = cand; kiv = cj; }
    float md = (lane < KNN) ? kdv : -FMAX;
    int   mi = (lane < KNN) ? kiv : -1;
    int   ml = lane;
#pragma unroll
    for (int o = 16; o; o >>= 1) {
        float od = __shfl_xor_sync(0xffffffffu, md, o);
        int   oi = __shfl_xor_sync(0xffffffffu, mi, o);
        int   ol = __shfl_xor_sync(0xffffffffu, ml, o);
        bool t = (od > md) || (od == md && oi > mi);
        if (t) { md = od; mi = oi; ml = ol; }
    }
    wv = md; wl = ml;
}

// =================== kernel 1: kNN on raw 2-D points ===================
__global__ void __launch_bounds__(256) knn1_kernel(const float* __restrict__ data) {
    __shared__ float2 sp[NPTS];
    int b = blockIdx.y;
    const float2* dp = (const float2*)(data + (size_t)b * NPTS * 2);
    for (int t = threadIdx.x; t < NPTS; t += 256) sp[t] = dp[t];
    __syncthreads();

    int tid = threadIdx.x, lane = tid & 31, wid = tid >> 5;
    int row0 = blockIdx.x * 64 + wid * 8;

    float2 xi[8]; float d2i[8];
#pragma unroll
    for (int r = 0; r < 8; r++) {
        xi[r] = sp[row0 + r];
        d2i[r] = xi[r].x * xi[r].x + xi[r].y * xi[r].y;
    }
    float kd[8], wv[8]; int ki[8], wl[8];
#pragma unroll
    for (int r = 0; r < 8; r++) { kd[r] = FMAX; ki[r] = 0x7fffffff; wv[r] = FMAX; wl[r] = 0; }

    for (int jc = 0; jc < NPTS / 32; jc++) {
        int jb = jc * 32;
        float2 xj = sp[jb + lane];
        float d2j = xj.x * xj.x + xj.y * xj.y;
#pragma unroll
        for (int r = 0; r < 8; r++) {
            float d = d2i[r] + d2j - 2.0f * (xi[r].x * xj.x + xi[r].y * xj.y);
            unsigned m = __ballot_sync(0xffffffffu, d < wv[r]);
            while (m) {
                int s = __ffs(m) - 1;
                float cand = __shfl_sync(0xffffffffu, d, s);
                topk_insert(cand, jb + s, kd[r], ki[r], wv[r], wl[r], lane);
                m &= ~(1u << s);
                m &= __ballot_sync(0xffffffffu, d < wv[r]);
            }
        }
    }
#pragma unroll
    for (int r = 0; r < 8; r++)
        if (lane < KNN)
            g_idx1[((size_t)b * NPTS + row0 + r) * KNN + lane] = ki[r];
}

// =================== kernel 2a: split+transpose W2/W3 to bf16 hi/lo ===================
__global__ void __launch_bounds__(256) splitw23_kernel(
    const float* __restrict__ c1w2, const float* __restrict__ c1w3)
{
    int idx = blockIdx.x * 256 + threadIdx.x;      // 8192
    int mat = idx >> 12, e = idx & 4095;
    int k = e >> 6, n = e & 63;
    const float* src = mat ? c1w3 : c1w2;
    float v = src[k * 64 + n];
    __nv_bfloat16 h = __float2bfloat16(v);
    __nv_bfloat16 l = __float2bfloat16(v - __bfloat162float(h));
    __nv_bfloat16* dst = mat ? g_w3s : g_w2s;
    dst[n * 136 + k] = h;
    dst[n * 136 + 64 + k] = l;
}

// =================== kernel 2b: EdgeConv1 via split-bf16 mma.sync (+x1 split fused) ===================
#define E1_SW1 0
#define E1_SB1 256
#define E1_SB2 320
#define E1_SB3 384
#define E1_SPC 448
#define E1_SXJ 960
#define E1B_W2 5120
#define E1B_W3 22528
#define E1B_H  39936
#define E1_BYTES (E1B_H + 160*272)

__global__ void __launch_bounds__(256) edge1_kernel(
    const float* __restrict__ data,
    const float* __restrict__ c1w1, const float* __restrict__ c1b1,
    const float* __restrict__ c1b2, const float* __restrict__ c1b3)
{
    extern __shared__ float sm[];
    char* smc = (char*)sm;
    unsigned sbase = (unsigned)__cvta_generic_to_shared(smc);
    int tid = threadIdx.x, lane = tid & 31, wid = tid >> 5;
    int wn = wid & 3, wm = wid >> 2;
    int base = blockIdx.x * 8;
    int b = base >> 12;

    if (tid < 256) sm[E1_SW1 + tid] = c1w1[tid];
    if (tid < 64) {
        sm[E1_SB1 + tid] = c1b1[tid];
        sm[E1_SB2 + tid] = c1b2[tid];
        sm[E1_SB3 + tid] = c1b3[tid];
    }
    for (int q = tid; q < 1088; q += 256)
        ((uint4*)(smc + E1B_W2))[q] = ((const uint4*)g_w2s)[q];
    for (int q = tid; q < 1088; q += 256)
        ((uint4*)(smc + E1B_W3))[q] = ((const uint4*)g_w3s)[q];
    __syncthreads();

    for (int idx = tid; idx < 512; idx += 256) {
        int p = idx >> 6, c = idx & 63;
        float xi0 = data[(size_t)(base + p) * 2 + 0];
        float xi1 = data[(size_t)(base + p) * 2 + 1];
        float wa = sm[E1_SW1 + c] - sm[E1_SW1 + 128 + c];
        float wb = sm[E1_SW1 + 64 + c] - sm[E1_SW1 + 192 + c];
        sm[E1_SPC + p * 64 + c] = fmaf(xi0, wa, fmaf(xi1, wb, sm[E1_SB1 + c]));
    }
    if (tid < 160) {
        int p = tid / 20, e = tid % 20;
        int j = g_idx1[(size_t)(base + p) * KNN + e];
        int gj = (b << 12) + j;
        sm[E1_SXJ + 2 * tid + 0] = data[(size_t)gj * 2 + 0];
        sm[E1_SXJ + 2 * tid + 1] = data[(size_t)gj * 2 + 1];
    }
    __syncthreads();

    for (int idx = tid; idx < 160 * 32; idx += 256) {
        int row = idx >> 5, cq = idx & 31;
        int p = row / 20, c0 = 2 * cq;
        float xj0 = sm[E1_SXJ + 2 * row], xj1 = sm[E1_SXJ + 2 * row + 1];
        float h0 = fmaxf(fmaf(xj0, sm[E1_SW1 + 128 + c0],
                     fmaf(xj1, sm[E1_SW1 + 192 + c0], sm[E1_SPC + p * 64 + c0])), 0.0f);
        float h1 = fmaxf(fmaf(xj0, sm[E1_SW1 + 128 + c0 + 1],
                     fmaf(xj1, sm[E1_SW1 + 192 + c0 + 1], sm[E1_SPC + p * 64 + c0 + 1])), 0.0f);
        unsigned hi, lo; split2(h0, h1, hi, lo);
        *(unsigned*)(smc + E1B_H + row * 272 + c0 * 2) = hi;
        *(unsigned*)(smc + E1B_H + row * 272 + 128 + c0 * 2) = lo;
    }
    __syncthreads();

    int arow = (lane & 7) + ((lane >> 3) & 1) * 8;
    int akb  = ((lane >> 4) & 1) * 16;
    int brow = (lane & 7) + ((lane >> 4) & 1) * 8;
    int bkb  = ((lane >> 3) & 1) * 16;
    unsigned aBase  = sbase + E1B_H  + (unsigned)(wm * 80 + arow) * 272 + akb;
    unsigned b2Base = sbase + E1B_W2 + (unsigned)(wn * 16 + brow) * 272 + bkb;
    unsigned b3Base = sbase + E1B_W3 + (unsigned)(wn * 16 + brow) * 272 + bkb;

    float bias2[2][2], bias3[2][2];
#pragma unroll
    for (int nf = 0; nf < 2; nf++) {
        int c = wn * 16 + nf * 8 + 2 * (lane & 3);
        bias2[nf][0] = sm[E1_SB2 + c]; bias2[nf][1] = sm[E1_SB2 + c + 1];
        bias3[nf][0] = sm[E1_SB3 + c]; bias3[nf][1] = sm[E1_SB3 + c + 1];
    }

    // ---- GEMM 1: H2 = relu(H1 @ W2 + b2) ----
    {
        float acc[5][2][4];
#pragma unroll
        for (int m = 0; m < 5; m++)
#pragma unroll
            for (int nf = 0; nf < 2; nf++)
#pragma unroll
                for (int e = 0; e < 4; e++) acc[m][nf][e] = 0.0f;
#pragma unroll
        for (int t = 0; t < 12; t++) {
            int ts = (t < 4) ? t : (t < 8 ? t - 4 : t - 8);
            int aoff = ((t >= 4 && t < 8) ? 128 : 0) + ts * 32;
            int boff = ((t >= 8) ? 128 : 0) + ts * 32;
            unsigned B0[4];
            ldsm4(B0[0], B0[1], B0[2], B0[3], b2Base + boff);
#pragma unroll
            for (int m = 0; m < 5; m++) {
                unsigned A0[4];
                ldsm4(A0[0], A0[1], A0[2], A0[3], aBase + m * (16 * 272) + aoff);
                mma_bf16(acc[m][0], A0[0], A0[1], A0[2], A0[3], B0[0], B0[1]);
                mma_bf16(acc[m][1], A0[0], A0[1], A0[2], A0[3], B0[2], B0[3]);
            }
        }
        __syncthreads();
#pragma unroll
        for (int m = 0; m < 5; m++) {
            int r0 = wm * 80 + m * 16 + (lane >> 2);
#pragma unroll
            for (int nf = 0; nf < 2; nf++) {
                int c0 = wn * 16 + nf * 8 + 2 * (lane & 3);
                float v0 = fmaxf(acc[m][nf][0] + bias2[nf][0], 0.0f);
                float v1 = fmaxf(acc[m][nf][1] + bias2[nf][1], 0.0f);
                float v2 = fmaxf(acc[m][nf][2] + bias2[nf][0], 0.0f);
                float v3 = fmaxf(acc[m][nf][3] + bias2[nf][1], 0.0f);
                unsigned hi, lo;
                split2(v0, v1, hi, lo);
                *(unsigned*)(smc + E1B_H + r0 * 272 + c0 * 2) = hi;
                *(unsigned*)(smc + E1B_H + r0 * 272 + 128 + c0 * 2) = lo;
                split2(v2, v3, hi, lo);
                *(unsigned*)(smc + E1B_H + (r0 + 8) * 272 + c0 * 2) = hi;
                *(unsigned*)(smc + E1B_H + (r0 + 8) * 272 + 128 + c0 * 2) = lo;
            }
        }
    }
    __syncthreads();

    // ---- GEMM 2: H3 = H2 @ W3 + b3 ----
    {
        float acc[5][2][4];
#pragma unroll
        for (int m = 0; m < 5; m++)
#pragma unroll
            for (int nf = 0; nf < 2; nf++)
#pragma unroll
                for (int e = 0; e < 4; e++) acc[m][nf][e] = 0.0f;
#pragma unroll
        for (int t = 0; t < 12; t++) {
            int ts = (t < 4) ? t : (t < 8 ? t - 4 : t - 8);
            int aoff = ((t >= 4 && t < 8) ? 128 : 0) + ts * 32;
            int boff = ((t >= 8) ? 128 : 0) + ts * 32;
            unsigned B0[4];
            ldsm4(B0[0], B0[1], B0[2], B0[3], b3Base + boff);
#pragma unroll
            for (int m = 0; m < 5; m++) {
                unsigned A0[4];
                ldsm4(A0[0], A0[1], A0[2], A0[3], aBase + m * (16 * 272) + aoff);
                mma_bf16(acc[m][0], A0[0], A0[1], A0[2], A0[3], B0[0], B0[1]);
                mma_bf16(acc[m][1], A0[0], A0[1], A0[2], A0[3], B0[2], B0[3]);
            }
        }
        __syncthreads();
        float* H3f = (float*)(smc + E1B_H);
#pragma unroll
        for (int m = 0; m < 5; m++) {
            int r0 = wm * 80 + m * 16 + (lane >> 2);
#pragma unroll
            for (int nf = 0; nf < 2; nf++) {
                int c0 = wn * 16 + nf * 8 + 2 * (lane & 3);
                *(float2*)&H3f[r0 * 68 + c0] =
                    make_float2(acc[m][nf][0] + bias3[nf][0], acc[m][nf][1] + bias3[nf][1]);
                *(float2*)&H3f[(r0 + 8) * 68 + c0] =
                    make_float2(acc[m][nf][2] + bias3[nf][0], acc[m][nf][3] + bias3[nf][1]);
            }
        }
    }
    __syncthreads();

    // max over 20 edge-rows per point; write x1 (+ fused bf16 split); stash for d2
    {
        const float* H3f = (const float*)(smc + E1B_H);
        for (int idx = tid; idx < 512; idx += 256) {
            int p = idx >> 6, c = idx & 63;
            float mx = H3f[(p * 20) * 68 + c];
#pragma unroll
            for (int e = 1; e < 20; e++) mx = fmaxf(mx, H3f[(p * 20 + e) * 68 + c]);
            g_x1[(size_t)(base + p) * 64 + c] = mx;
            __nv_bfloat16 h = __float2bfloat16(mx);
            __nv_bfloat16 l = __float2bfloat16(mx - __bfloat162float(h));
            g_xsplit[(size_t)(base + p) * 384 + c] = h;
            g_xsplit[(size_t)(base + p) * 384 + 192 + c] = l;
            sm[E1_SPC + idx] = mx;
        }
    }
    __syncthreads();
    {
        int w = tid >> 5;
        float v0 = sm[E1_SPC + w * 64 + lane];
        float v1 = sm[E1_SPC + w * 64 + 32 + lane];
        float s = v0 * v0 + v1 * v1;
#pragma unroll
        for (int o = 16; o; o >>= 1) s += __shfl_xor_sync(0xffffffffu, s, o);
        if (lane == 0) g_d2[base + w] = s;
    }
}

// =================== kernel 3: EdgeConv2 per-point linear parts (16 pts/block) ===================
__global__ void __launch_bounds__(128) prep2_kernel(
    const float* __restrict__ c2w1, const float* __restrict__ c2b1)
{
    __shared__ float sx[16][64];
    int c = threadIdx.x;
    int base = blockIdx.x * 16;
    for (int idx = c; idx < 1024; idx += 128) {
        int p = idx >> 6, d = idx & 63;
        sx[p][d] = g_x1[(size_t)(base + p) * 64 + d];
    }
    __syncthreads();
    float accA[16], accC[16];
    float bc = c2b1[c];
#pragma unroll
    for (int p = 0; p < 16; p++) { accA[p] = bc; accC[p] = 0.0f; }
    for (int d = 0; d < 64; d++) {
        float wt = c2w1[d * 128 + c];
        float wbv = c2w1[(d + 64) * 128 + c];
        float wd = wt - wbv;
#pragma unroll
        for (int p = 0; p < 16; p++) {
            float xv = sx[p][d];
            accA[p] = fmaf(xv, wd, accA[p]);
            accC[p] = fmaf(xv, wbv, accC[p]);
        }
    }
#pragma unroll
    for (int p = 0; p < 16; p++) {
        g_A2[(size_t)(base + p) * 128 + c] = accA[p];
        g_C2[(size_t)(base + p) * 128 + c] = accC[p];
    }
}

// =================== kernel 4: knn2 — R4/R9 proven config (32 rows, 2 blocks/SM) ===================
#define KP 68
#define KN2_AS   (32 * KP)
#define KN2_BS   (128 * KP)
#define KN2_SMEM_FLOATS (KN2_AS + 2 * KN2_BS + 2 * 128)
#define KN2_SMEM_BYTES  (KN2_SMEM_FLOATS * 4)

__global__ void __launch_bounds__(256, 2) knn2_kernel() {
    extern __shared__ float sm[];
    float* As   = sm;
    float* Bs0  = sm + KN2_AS;
    float* d2s0 = sm + KN2_AS + 2 * KN2_BS;

    int b = blockIdx.y;
    int it0 = blockIdx.x * 32;
    int tid = threadIdx.x, lane = tid & 31, wid = tid >> 5;
    const float* xb = g_x1 + (size_t)b * NPTS * 64;

#pragma unroll
    for (int t = 0; t < 2; t++) {
        int idx = tid + t * 256;
        int i = idx >> 4, kq = idx & 15;
        *(float4*)(As + i * KP + kq * 4) =
            *(const float4*)(xb + (size_t)(it0 + i) * 64 + kq * 4);
    }
    float d2i[4];
#pragma unroll
    for (int r = 0; r < 4; r++) d2i[r] = g_d2[b * NPTS + it0 + wid * 4 + r];

    float kd[4], wv[4]; int ki[4], wl[4];
#pragma unroll
    for (int r = 0; r < 4; r++) { kd[r] = FMAX; ki[r] = 0x7fffffff; wv[r] = FMAX; wl[r] = 0; }

    {
        float* B = Bs0;
#pragma unroll
        for (int t = 0; t < 8; t++) {
            int idx = tid + t * 256;
            int j = idx >> 4, kq = idx & 15;
            cp_async16(B + j * KP + kq * 4, xb + (size_t)j * 64 + kq * 4);
        }
        if (tid < 32) cp_async16(d2s0 + tid * 4, g_d2 + b * NPTS + tid * 4);
        cp_async_commit();
    }

    for (int jt = 0; jt < 32; jt++) {
        int buf = jt & 1;
        cp_async_wait0();
        __syncthreads();

        if (jt + 1 < 32) {
            int jb1 = (jt + 1) * 128;
            float* B = Bs0 + (buf ^ 1) * KN2_BS;
#pragma unroll
            for (int t = 0; t < 8; t++) {
                int idx = tid + t * 256;
                int j = idx >> 4, kq = idx & 15;
                cp_async16(B + j * KP + kq * 4, xb + (size_t)(jb1 + j) * 64 + kq * 4);
            }
            if (tid < 32) cp_async16(d2s0 + (buf ^ 1) * 128 + tid * 4,
                                     g_d2 + b * NPTS + jb1 + tid * 4);
            cp_async_commit();
        }

        const float* B = Bs0 + buf * KN2_BS;
        const float* d2s = d2s0 + buf * 128;
        int jb = jt * 128;

        u64t acc2[4][4];
#pragma unroll
        for (int r = 0; r < 4; r++)
#pragma unroll
            for (int jj = 0; jj < 4; jj++) acc2[r][jj] = 0ull;

#pragma unroll 8
        for (int kq = 0; kq < 16; kq++) {
            F4U a[4], bb[4];
#pragma unroll
            for (int r = 0; r < 4; r++)
                a[r].f = *(const float4*)(As + (wid * 4 + r) * KP + kq * 4);
#pragma unroll
            for (int jj = 0; jj < 4; jj++)
                bb[jj].f = *(const float4*)(B + (jj * 32 + lane) * KP + kq * 4);
#pragma unroll
            for (int r = 0; r < 4; r++)
#pragma unroll
                for (int jj = 0; jj < 4; jj++) {
                    acc2[r][jj] = fma2(a[r].u[0], bb[jj].u[0], acc2[r][jj]);
                    acc2[r][jj] = fma2(a[r].u[1], bb[jj].u[1], acc2[r][jj]);
                }
        }

        float d2jv[4];
#pragma unroll
        for (int jj = 0; jj < 4; jj++) d2jv[jj] = d2s[jj * 32 + lane];

#pragma unroll
        for (int r = 0; r < 4; r++) {
#pragma unroll
            for (int jj = 0; jj < 4; jj++) {
                float2 v = up2(acc2[r][jj]);
                float dv = d2i[r] + d2jv[jj] - 2.0f * (v.x + v.y);
                unsigned m = __ballot_sync(0xffffffffu, dv < wv[r]);
                while (m) {
                    int s = __ffs(m) - 1;
                    float cand = __shfl_sync(0xffffffffu, dv, s);
                    topk_insert(cand, jb + jj * 32 + s, kd[r], ki[r], wv[r], wl[r], lane);
                    m &= ~(1u << s);
                    m &= __ballot_sync(0xffffffffu, dv < wv[r]);
                }
            }
        }
    }
#pragma unroll
    for (int r = 0; r < 4; r++)
        if (lane < KNN)
            g_idx2[((size_t)b * NPTS + it0 + wid * 4 + r) * KNN + lane] = ki[r];
}

// =================== kernel 5: EdgeConv2 gather-max (+x2 split fused) ===================
__global__ void __launch_bounds__(128) edge2max_kernel() {
    __shared__ int sj[4][KNN];
    int p0 = blockIdx.x * 4;
    int c = threadIdx.x;
    if (c < 4 * KNN) sj[c / KNN][c % KNN] = g_idx2[(size_t)(p0 + c / KNN) * KNN + c % KNN];
    __syncthreads();
#pragma unroll
    for (int q = 0; q < 4; q++) {
        int gp = p0 + q;
        int b = gp >> 12;
        float m = -FMAX;
#pragma unroll
        for (int e = 0; e < KNN; e++)
            m = fmaxf(m, g_C2[((size_t)b * NPTS + sj[q][e]) * 128 + c]);
        float v = g_A2[(size_t)gp * 128 + c] + m;
        g_x2[(size_t)gp * 128 + c] = v;
        __nv_bfloat16 h = __float2bfloat16(v);
        __nv_bfloat16 l = __float2bfloat16(v - __bfloat162float(h));
        g_xsplit[(size_t)gp * 384 + 64 + c] = h;
        g_xsplit[(size_t)gp * 384 + 192 + 64 + c] = l;
    }
}

// =================== kernel 6b: split + transpose lin1_w ===================
__global__ void __launch_bounds__(256) splitw_kernel(const float* __restrict__ lin1_w) {
    int idx = blockIdx.x * 256 + threadIdx.x;
    int n = idx / 192, k = idx - n * 192;
    float v = lin1_w[(size_t)k * 1024 + n];
    __nv_bfloat16 h = __float2bfloat16(v);
    __nv_bfloat16 l = __float2bfloat16(v - __bfloat162float(h));
    g_wsplit[(size_t)n * 384 + k] = h;
    g_wsplit[(size_t)n * 384 + 192 + k] = l;
}

// =================== kernel 6c: lin1 via split-bf16 mma.sync + fused row-max ===================
#define LM_STR  784
#define LM_WS   0
#define LM_XS   (128 * LM_STR)
#define LM_XSZ  (32 * LM_STR)
#define LM_SMEM (LM_XS + 2 * LM_XSZ)

__global__ void __launch_bounds__(256, 1) lin1mma_kernel() {
    extern __shared__ char smc[];
    unsigned sbase = (unsigned)__cvta_generic_to_shared(smc);
    int tid = threadIdx.x, lane = tid & 31, w = tid >> 5;
    int cc = blockIdx.x, rc = blockIdx.y, b = blockIdx.z;
    const __nv_bfloat16* xs = g_xsplit + (size_t)(b * NPTS + rc * 1024) * 384;
    const __nv_bfloat16* ws = g_wsplit + (size_t)cc * 128 * 384;

    for (int q = tid; q < 128 * 48; q += 256) {
        int n = q / 48, u = q - n * 48;
        cp_async16(smc + LM_WS + n * LM_STR + u * 16, (const char*)(ws + (size_t)n * 384) + u * 16);
    }
    for (int q = tid; q < 32 * 48; q += 256) {
        int r = q / 48, u = q - r * 48;
        cp_async16(smc + LM_XS + r * LM_STR + u * 16, (const char*)(xs + (size_t)r * 384) + u * 16);
    }
    cp_async_commit();

    int arow = (lane & 7) + ((lane >> 3) & 1) * 8;
    int akb  = ((lane >> 4) & 1) * 16;
    int brow = (lane & 7) + ((lane >> 4) & 1) * 8;
    int bkb  = ((lane >> 3) & 1) * 16;
    unsigned bAddr0 = sbase + LM_WS + (unsigned)(w * 16 + brow) * LM_STR + bkb;

    float rm[2][2];
#pragma unroll
    for (int nf = 0; nf < 2; nf++) { rm[nf][0] = -FMAX; rm[nf][1] = -FMAX; }

    for (int ch = 0; ch < 32; ch++) {
        int buf = ch & 1;
        cp_async_wait0();
        __syncthreads();

        if (ch + 1 < 32) {
            char* Xd = smc + LM_XS + (buf ^ 1) * LM_XSZ;
            const __nv_bfloat16* src = xs + (size_t)(ch + 1) * 32 * 384;
            for (int q = tid; q < 32 * 48; q += 256) {
                int r = q / 48, u = q - r * 48;
                cp_async16(Xd + r * LM_STR + u * 16, (const char*)(src + (size_t)r * 384) + u * 16);
            }
            cp_async_commit();
        }

        unsigned aAddr0 = sbase + LM_XS + buf * LM_XSZ + (unsigned)arow * LM_STR + akb;
        float acc[2][2][4];
#pragma unroll
        for (int m = 0; m < 2; m++)
#pragma unroll
            for (int nf = 0; nf < 2; nf++)
#pragma unroll
                for (int e = 0; e < 4; e++) acc[m][nf][e] = 0.0f;

#pragma unroll
        for (int t = 0; t < 36; t++) {
            int aoff = ((t < 12) ? t : t - 12) * 32;
            int boff = ((t < 24) ? t : t - 24) * 32;
            unsigned A0[4], A1[4], B0[4];
            ldsm4(A0[0], A0[1], A0[2], A0[3], aAddr0 + aoff);
            ldsm4(A1[0], A1[1], A1[2], A1[3], aAddr0 + 16 * LM_STR + aoff);
            ldsm4(B0[0], B0[1], B0[2], B0[3], bAddr0 + boff);
            mma_bf16(acc[0][0], A0[0], A0[1], A0[2], A0[3], B0[0], B0[1]);
            mma_bf16(acc[0][1], A0[0], A0[1], A0[2], A0[3], B0[2], B0[3]);
            mma_bf16(acc[1][0], A1[0], A1[1], A1[2], A1[3], B0[0], B0[1]);
            mma_bf16(acc[1][1], A1[0], A1[1], A1[2], A1[3], B0[2], B0[3]);
        }
#pragma unroll
        for (int nf = 0; nf < 2; nf++) {
            rm[nf][0] = fmaxf(rm[nf][0], fmaxf(fmaxf(acc[0][nf][0], acc[0][nf][2]),
                                               fmaxf(acc[1][nf][0], acc[1][nf][2])));
            rm[nf][1] = fmaxf(rm[nf][1], fmaxf(fmaxf(acc[0][nf][1], acc[0][nf][3]),
                                               fmaxf(acc[1][nf][1], acc[1][nf][3])));
        }
    }
#pragma unroll
    for (int o = 4; o <= 16; o <<= 1)
#pragma unroll
        for (int nf = 0; nf < 2; nf++) {
            rm[nf][0] = fmaxf(rm[nf][0], __shfl_xor_sync(0xffffffffu, rm[nf][0], o));
            rm[nf][1] = fmaxf(rm[nf][1], __shfl_xor_sync(0xffffffffu, rm[nf][1], o));
        }
    if (lane < 4) {
#pragma unroll
        for (int nf = 0; nf < 2; nf++) {
            int col = cc * 128 + w * 16 + nf * 8 + 2 * lane;
            g_pmax[((size_t)b * 16 + rc) * 1024 + col]     = rm[nf][0];
            g_pmax[((size_t)b * 16 + rc) * 1024 + col + 1] = rm[nf][1];
        }
    }
}

// =================== kernel 7: reduce partial maxes + bias ===================
__global__ void __launch_bounds__(1024) redmax_kernel(const float* __restrict__ lin1_b) {
    int b = blockIdx.x, c = threadIdx.x;
    float m = -FMAX;
#pragma unroll
    for (int t = 0; t < 4; t++) m = fmaxf(m, g_pmax[((size_t)b * 16 + t) * 1024 + c]);
    g_gmax[b * 1024 + c] = m + lin1_b[c];
}

// =================== kernel 8a: head GEMV1 split over k-chunks ===================
__global__ void __launch_bounds__(512) head1_kernel(const float* __restrict__ mw1) {
    __shared__ float sg[128];
    int kc = blockIdx.x, b = blockIdx.y, t = threadIdx.x;
    if (t < 128) sg[t] = g_gmax[b * 1024 + kc * 128 + t];
    __syncthreads();
    float acc = 0.0f;
#pragma unroll 4
    for (int d = 0; d < 128; d++)
        acc = fmaf(sg[d], mw1[(size_t)(kc * 128 + d) * 512 + t], acc);
    g_hpart[(size_t)(b * 8 + kc) * 512 + t] = acc;
}

// =================== kernel 8b: head rest + log_softmax ===================
__global__ void __launch_bounds__(512) head2_kernel(
    const float* __restrict__ mb1,
    const float* __restrict__ mw2, const float* __restrict__ mb2,
    const float* __restrict__ mw3, const float* __restrict__ mb3,
    float* __restrict__ out)
{
    __shared__ float s1[512];
    __shared__ float s2[256];
    __shared__ float s3[10];
    int b = blockIdx.x, t = threadIdx.x;

    float a = mb1[t];
#pragma unroll
    for (int kc = 0; kc < 8; kc++) a += g_hpart[(size_t)(b * 8 + kc) * 512 + t];
    s1[t] = fmaxf(a, 0.0f);
    __syncthreads();

    if (t < 256) {
        float acc = mb2[t];
#pragma unroll 4
        for (int d = 0; d < 512; d++) acc = fmaf(s1[d], mw2[d * 256 + t], acc);
        s2[t] = fmaxf(acc, 0.0f);
    }
    __syncthreads();

    if (t < 10) {
        float acc = mb3[t];
        for (int d = 0; d < 256; d++) acc = fmaf(s2[d], mw3[d * 10 + t], acc);
        s3[t] = acc;
    }
    __syncthreads();

    if (t == 0) {
        float mx = s3[0];
        for (int j = 1; j < 10; j++) mx = fmaxf(mx, s3[j]);
        float s = 0.0f;
        for (int j = 0; j < 10; j++) s += expf(s3[j] - mx);
        float l = logf(s) + mx;
        for (int j = 0; j < 10; j++) out[b * 10 + j] = s3[j] - l;
    }
}

// =================== launch ===================
extern "C" void kernel_launch(void* const* d_in, const int* in_sizes, int n_in,
                              void* d_out, int out_size) {
    const float* data   = (const float*)d_in[0];
    const float* c1w1   = (const float*)d_in[1];
    const float* c1b1   = (const float*)d_in[2];
    const float* c1w2   = (const float*)d_in[3];
    const float* c1b2   = (const float*)d_in[4];
    const float* c1w3   = (const float*)d_in[5];
    const float* c1b3   = (const float*)d_in[6];
    const float* c2w1   = (const float*)d_in[7];
    const float* c2b1   = (const float*)d_in[8];
    const float* lin1_w = (const float*)d_in[9];
    const float* lin1_b = (const float*)d_in[10];
    const float* mw1    = (const float*)d_in[11];
    const float* mb1    = (const float*)d_in[12];
    const float* mw2    = (const float*)d_in[13];
    const float* mb2    = (const float*)d_in[14];
    const float* mw3    = (const float*)d_in[15];
    const float* mb3    = (const float*)d_in[16];
    float* out = (float*)d_out;

    cudaFuncSetAttribute(edge1_kernel, cudaFuncAttributeMaxDynamicSharedMemorySize, E1_BYTES);
    cudaFuncSetAttribute(knn2_kernel, cudaFuncAttributeMaxDynamicSharedMemorySize, KN2_SMEM_BYTES);
    cudaFuncSetAttribute(lin1mma_kernel, cudaFuncAttributeMaxDynamicSharedMemorySize, LM_SMEM);

    knn1_kernel<<<dim3(64, 8), 256>>>(data);
    splitw23_kernel<<<32, 256>>>(c1w2, c1w3);
    edge1_kernel<<<BATCH * NPTS / 8, 256, E1_BYTES>>>(data, c1w1, c1b1, c1b2, c1b3);
    prep2_kernel<<<BATCH * NPTS / 16, 128>>>(c2w1, c2b1);
    knn2_kernel<<<dim3(128, 8), 256, KN2_SMEM_BYTES>>>();
    edge2max_kernel<<<BATCH * NPTS / 4, 128>>>();
    splitw_kernel<<<1024 * 192 / 256, 256>>>(lin1_w);
    lin1mma_kernel<<<dim3(8, 4, 8), 256, LM_SMEM>>>();
    redmax_kernel<<<8, 1024>>>(lin1_b);
    head1_kernel<<<dim3(8, 8), 512>>>(mw1);
    head2_kernel<<<8, 512>>>(mb1, mw2, mb2, mw3, mb3, out);
}